// round 5
// baseline (speedup 1.0000x reference)
#include <cuda_runtime.h>
#include <cuda_bf16.h>
#include <cstdint>
#include <math.h>

#define MAXN 100000
#define MAXE 1600000
#define PITCH 136   // bf16 elements per smem/W-image row (128 + 8 pad)

// ---------------- scratch (device globals; no allocation allowed) ----------
__device__ alignas(256) __nv_bfloat16 g_tmpb[(size_t)MAXN * 128];  // GEMM out (bf16)
__device__ alignas(256) float g_h[(size_t)MAXN * 128];             // hidden (fp32)
__device__ float g_dis[MAXN];
__device__ int   g_deg[MAXN];
__device__ int   g_rowptr[MAXN + 1];
__device__ int   g_cur[MAXN];
__device__ alignas(16) unsigned long long g_ecw[MAXE];  // packed {w_bits, col}
__device__ int   g_aux[1024];
// W^T images, [BN rows][PITCH cols] bf16, hi/mid split
__device__ alignas(16) __nv_bfloat16 g_w0img[2][128 * PITCH];
__device__ alignas(16) __nv_bfloat16 g_w1img[2][128 * PITCH];
__device__ alignas(16) __nv_bfloat16 g_w2img[2][64 * PITCH];

// ---------------- helpers ---------------------------------------------------
__device__ __forceinline__ uint32_t smem_u32(const void* p) {
    uint32_t a;
    asm("{ .reg .u64 t; cvta.to.shared.u64 t, %1; cvt.u32.u64 %0, t; }" : "=r"(a) : "l"(p));
    return a;
}
__device__ __forceinline__ void ldmx4(uint32_t& a0, uint32_t& a1, uint32_t& a2, uint32_t& a3,
                                      uint32_t addr) {
    asm volatile("ldmatrix.sync.aligned.m8n8.x4.shared.b16 {%0,%1,%2,%3}, [%4];"
                 : "=r"(a0), "=r"(a1), "=r"(a2), "=r"(a3) : "r"(addr));
}
__device__ __forceinline__ void ldmx2(uint32_t& b0, uint32_t& b1, uint32_t addr) {
    asm volatile("ldmatrix.sync.aligned.m8n8.x2.shared.b16 {%0,%1}, [%2];"
                 : "=r"(b0), "=r"(b1) : "r"(addr));
}
__device__ __forceinline__ void mma16816(float* c, uint32_t a0, uint32_t a1, uint32_t a2,
                                         uint32_t a3, uint32_t b0, uint32_t b1) {
    asm volatile("mma.sync.aligned.m16n8k16.row.col.f32.bf16.bf16.f32 "
                 "{%0,%1,%2,%3}, {%4,%5,%6,%7}, {%8,%9}, {%0,%1,%2,%3};"
                 : "+f"(c[0]), "+f"(c[1]), "+f"(c[2]), "+f"(c[3])
                 : "r"(a0), "r"(a1), "r"(a2), "r"(a3), "r"(b0), "r"(b1));
}
// unpack 8 bf16 (uint4) -> 8 floats
__device__ __forceinline__ void bf8_to_f32(const uint4& u, float* f) {
    float2 p;
    p = __bfloat1622float2(reinterpret_cast<const __nv_bfloat162&>(u.x)); f[0] = p.x; f[1] = p.y;
    p = __bfloat1622float2(reinterpret_cast<const __nv_bfloat162&>(u.y)); f[2] = p.x; f[3] = p.y;
    p = __bfloat1622float2(reinterpret_cast<const __nv_bfloat162&>(u.z)); f[4] = p.x; f[5] = p.y;
    p = __bfloat1622float2(reinterpret_cast<const __nv_bfloat162&>(u.w)); f[6] = p.x; f[7] = p.y;
}

// ---------------- degree / normalization / CSR build -----------------------
__global__ void k_deg_zero(int n) {
    int i = blockIdx.x * blockDim.x + threadIdx.x;
    if (i < n) g_deg[i] = 0;
}
__global__ void k_count(const int* __restrict__ rows, int E) {
    int e = blockIdx.x * blockDim.x + threadIdx.x;
    if (e < E) atomicAdd(&g_deg[rows[e]], 1);
}
// fused: dis computation + block-wide exclusive scan of deg
__global__ void k_disscan1(int n) {
    __shared__ int sh[1024];
    int tid = threadIdx.x;
    int i = blockIdx.x * 1024 + tid;
    int v = (i < n) ? g_deg[i] : 0;
    if (i < n) g_dis[i] = rsqrtf((float)(v + 1));   // +1 self-loop
    sh[tid] = v;
    __syncthreads();
#pragma unroll
    for (int off = 1; off < 1024; off <<= 1) {
        int t = (tid >= off) ? sh[tid - off] : 0;
        __syncthreads();
        sh[tid] += t;
        __syncthreads();
    }
    if (i < n) g_rowptr[i] = sh[tid] - v;
    if (tid == 1023) g_aux[blockIdx.x] = sh[1023];
}
__global__ void k_scan2(int nb) {   // parallel exclusive scan of block sums (nb <= 128)
    __shared__ int sh[128];
    int t = threadIdx.x;
    int v = (t < nb) ? g_aux[t] : 0;
    sh[t] = v;
    __syncthreads();
#pragma unroll
    for (int off = 1; off < 128; off <<= 1) {
        int x = (t >= off) ? sh[t - off] : 0;
        __syncthreads();
        sh[t] += x;
        __syncthreads();
    }
    if (t < nb) g_aux[t] = sh[t] - v;
}
__global__ void k_scan3(int n, int E) {
    int i = blockIdx.x * 1024 + threadIdx.x;
    if (i < n) {
        int v = g_rowptr[i] + g_aux[blockIdx.x];
        g_rowptr[i] = v;
        g_cur[i] = v;
    }
    if (blockIdx.x == 0 && threadIdx.x == 0) g_rowptr[n] = E;
}
__global__ void k_fill(const int* __restrict__ rows, const int* __restrict__ cols, int E) {
    int e = blockIdx.x * blockDim.x + threadIdx.x;
    if (e >= E) return;
    int r = rows[e], c = cols[e];
    int pos = atomicAdd(&g_cur[r], 1);
    float w = g_dis[r] * g_dis[c];
    g_ecw[pos] = ((unsigned long long)__float_as_uint(w) << 32) | (unsigned)c;
}

// ---------------- fused weight split: all 3 layers in one kernel -----------
__global__ void k_split_all(const float* __restrict__ W0, const float* __restrict__ W1,
                            const float* __restrict__ W2)
{
    int idx = blockIdx.x * blockDim.x + threadIdx.x;
    const float* W;
    __nv_bfloat16 *hi, *mid;
    int BN, off;
    if (idx < 16384)        { W = W0; hi = g_w0img[0]; mid = g_w0img[1]; BN = 128; off = idx; }
    else if (idx < 32768)   { W = W1; hi = g_w1img[0]; mid = g_w1img[1]; BN = 128; off = idx - 16384; }
    else if (idx < 40960)   { W = W2; hi = g_w2img[0]; mid = g_w2img[1]; BN = 64;  off = idx - 32768; }
    else return;
    int k = off / BN, j = off % BN;
    float v = W[off];
    __nv_bfloat16 h = __float2bfloat16_rn(v);
    float r = v - __bfloat162float(h);
    hi [j * PITCH + k] = h;
    mid[j * PITCH + k] = __float2bfloat16_rn(r);
}

// ---------------- GEMM via mma.sync bf16 split ------------------------------
template <int BN, bool RELU>
__global__ __launch_bounds__(256) void k_gemm_mma(
    const float* __restrict__ A,
    const __nv_bfloat16* __restrict__ WThi, const __nv_bfloat16* __restrict__ WTmid,
    __nv_bfloat16* __restrict__ C, int n)
{
    extern __shared__ __nv_bfloat16 sm[];
    __nv_bfloat16* Ahi = sm;                       // [64][PITCH]
    __nv_bfloat16* Ami = sm + 64 * PITCH;
    __nv_bfloat16* Whi = sm + 2 * 64 * PITCH;      // [BN][PITCH] x2 (hi, mid)

    const int tid = threadIdx.x;
    const int wid = tid >> 5;
    const int lane = tid & 31;
    const int row0 = blockIdx.x * 64;
    constexpr int NT = BN / 32;
    constexpr uint32_t AOFF = 64 * PITCH * 2;
    constexpr uint32_t WOFF = BN * PITCH * 2;

    {
        const float4* s0 = (const float4*)WThi;
        const float4* s1 = (const float4*)WTmid;
        float4* d0 = (float4*)Whi;
        float4* d1 = (float4*)(Whi + BN * PITCH);
        constexpr int NV = BN * PITCH / 8;
#pragma unroll
        for (int i = tid; i < NV; i += 256) { d0[i] = s0[i]; d1[i] = s1[i]; }
    }
    {
        const int r = tid >> 2;
        const int q = tid & 3;
        const int gr = row0 + r;
        const bool valid = gr < n;
        const float4* arow = (const float4*)(A + (size_t)(valid ? gr : 0) * 128);
#pragma unroll
        for (int i = 0; i < 8; i++) {
            int c = q * 32 + i * 4;
            float4 v = valid ? arow[c >> 2] : make_float4(0.f, 0.f, 0.f, 0.f);
            if (RELU) {
                v.x = fmaxf(v.x, 0.f); v.y = fmaxf(v.y, 0.f);
                v.z = fmaxf(v.z, 0.f); v.w = fmaxf(v.w, 0.f);
            }
            __nv_bfloat162 h01 = __float22bfloat162_rn(make_float2(v.x, v.y));
            __nv_bfloat162 h23 = __float22bfloat162_rn(make_float2(v.z, v.w));
            float2 f01 = __bfloat1622float2(h01);
            float2 f23 = __bfloat1622float2(h23);
            __nv_bfloat162 m01 = __float22bfloat162_rn(make_float2(v.x - f01.x, v.y - f01.y));
            __nv_bfloat162 m23 = __float22bfloat162_rn(make_float2(v.z - f23.x, v.w - f23.y));
            *reinterpret_cast<uint2*>(Ahi + r * PITCH + c) =
                make_uint2(reinterpret_cast<uint32_t&>(h01), reinterpret_cast<uint32_t&>(h23));
            *reinterpret_cast<uint2*>(Ami + r * PITCH + c) =
                make_uint2(reinterpret_cast<uint32_t&>(m01), reinterpret_cast<uint32_t&>(m23));
        }
    }
    __syncthreads();

    const int warpM = wid & 1;
    const int warpN = wid >> 1;

    float acc[2][NT][4];
#pragma unroll
    for (int mi = 0; mi < 2; mi++)
#pragma unroll
        for (int ni = 0; ni < NT; ni++)
#pragma unroll
            for (int j = 0; j < 4; j++) acc[mi][ni][j] = 0.f;

    uint32_t a_addr[2], b_addr[NT];
#pragma unroll
    for (int mi = 0; mi < 2; mi++) {
        int r = warpM * 32 + mi * 16 + (lane & 15);
        int c = ((lane >> 4) << 3);
        a_addr[mi] = smem_u32(Ahi + r * PITCH + c);
    }
#pragma unroll
    for (int ni = 0; ni < NT; ni++) {
        int r = warpN * (BN / 4) + ni * 8 + (lane & 7);
        int c = ((lane >> 3) & 1) * 8;
        b_addr[ni] = smem_u32(Whi + r * PITCH + c);
    }

#pragma unroll
    for (int p = 0; p < 3; p++) {
        const uint32_t ao = (p == 2) ? AOFF : 0u;
        const uint32_t bo = (p == 1) ? WOFF : 0u;
#pragma unroll
        for (int kk = 0; kk < 8; kk++) {
            const uint32_t ko = kk * 32;
            uint32_t a[2][4];
#pragma unroll
            for (int mi = 0; mi < 2; mi++)
                ldmx4(a[mi][0], a[mi][1], a[mi][2], a[mi][3], a_addr[mi] + ao + ko);
            uint32_t b[NT][2];
#pragma unroll
            for (int ni = 0; ni < NT; ni++)
                ldmx2(b[ni][0], b[ni][1], b_addr[ni] + bo + ko);
#pragma unroll
            for (int mi = 0; mi < 2; mi++)
#pragma unroll
                for (int ni = 0; ni < NT; ni++)
                    mma16816(acc[mi][ni], a[mi][0], a[mi][1], a[mi][2], a[mi][3],
                             b[ni][0], b[ni][1]);
        }
    }

#pragma unroll
    for (int mi = 0; mi < 2; mi++) {
        int r = row0 + warpM * 32 + mi * 16 + (lane >> 2);
#pragma unroll
        for (int ni = 0; ni < NT; ni++) {
            int c = warpN * (BN / 4) + ni * 8 + (lane & 3) * 2;
            if (r < n) {
                __nv_bfloat162 v = __float22bfloat162_rn(make_float2(acc[mi][ni][0], acc[mi][ni][1]));
                *reinterpret_cast<__nv_bfloat162*>(C + (size_t)r * BN + c) = v;
            }
            if (r + 8 < n) {
                __nv_bfloat162 v = __float22bfloat162_rn(make_float2(acc[mi][ni][2], acc[mi][ni][3]));
                *reinterpret_cast<__nv_bfloat162*>(C + (size_t)(r + 8) * BN + c) = v;
            }
        }
    }
}

// ---------------- SPMM D=128: half-warp per edge, uint4 gathers ------------
// out[r] = bias + dis[r]^2 * tmp[r] + sum_j w_j * tmp[col_j]
__global__ __launch_bounds__(256) void k_spmm128(
    const __nv_bfloat16* __restrict__ tmp, const float* __restrict__ bias,
    float* __restrict__ out, int n)
{
    int warp = (blockIdx.x * 256 + threadIdx.x) >> 5;
    int lane = threadIdx.x & 31;
    if (warp >= n) return;
    int beg = __ldg(&g_rowptr[warp]);
    int end = __ldg(&g_rowptr[warp + 1]);
    const int hl = lane >> 4;           // half index
    const int ll = lane & 15;           // lane within half; covers cols ll*8..+7

    float acc[8];
    if (hl == 0) {                       // half 0 seeds bias
        float4 b0 = *(const float4*)(bias + ll * 8);
        float4 b1 = *(const float4*)(bias + ll * 8 + 4);
        acc[0] = b0.x; acc[1] = b0.y; acc[2] = b0.z; acc[3] = b0.w;
        acc[4] = b1.x; acc[5] = b1.y; acc[6] = b1.z; acc[7] = b1.w;
    } else {                             // half 1 seeds self-loop
        float ds = g_dis[warp];
        float sw = ds * ds;
        uint4 u = *(const uint4*)(tmp + (size_t)warp * 128 + ll * 8);
        float f[8]; bf8_to_f32(u, f);
#pragma unroll
        for (int k = 0; k < 8; k++) acc[k] = sw * f[k];
    }

    for (int e = beg; e < end; e += 32) {
        unsigned long long cw = 0;
        if (e + lane < end) cw = __ldg(&g_ecw[e + lane]);
        int cnt = min(32, end - e);
#pragma unroll 4
        for (int j = 0; j < cnt; j += 2) {   // 2 edges per iteration
            unsigned long long s = __shfl_sync(0xffffffffu, cw, j + hl);
            int   cj = (int)(unsigned)s;
            float wj = __uint_as_float((unsigned)(s >> 32));   // 0 past end -> row 0, no-op
            uint4 u = *(const uint4*)(tmp + (size_t)cj * 128 + ll * 8);
            float f[8]; bf8_to_f32(u, f);
#pragma unroll
            for (int k = 0; k < 8; k++) acc[k] = fmaf(wj, f[k], acc[k]);
        }
    }
#pragma unroll
    for (int k = 0; k < 8; k++) acc[k] += __shfl_xor_sync(0xffffffffu, acc[k], 16);
    float4 v = make_float4(acc[hl * 4 + 0], acc[hl * 4 + 1], acc[hl * 4 + 2], acc[hl * 4 + 3]);
    *(float4*)(out + (size_t)warp * 128 + ll * 8 + hl * 4) = v;
}

// ---------------- SPMM D=64: quarter-warp per edge -------------------------
__global__ __launch_bounds__(256) void k_spmm64(
    const __nv_bfloat16* __restrict__ tmp, const float* __restrict__ bias,
    float* __restrict__ out, int n)
{
    int warp = (blockIdx.x * 256 + threadIdx.x) >> 5;
    int lane = threadIdx.x & 31;
    if (warp >= n) return;
    int beg = __ldg(&g_rowptr[warp]);
    int end = __ldg(&g_rowptr[warp + 1]);
    const int q  = lane >> 3;           // quarter index
    const int ql = lane & 7;            // covers cols ql*8..+7

    float acc[8];
    if (q == 0) {
        float4 b0 = *(const float4*)(bias + ql * 8);
        float4 b1 = *(const float4*)(bias + ql * 8 + 4);
        acc[0] = b0.x; acc[1] = b0.y; acc[2] = b0.z; acc[3] = b0.w;
        acc[4] = b1.x; acc[5] = b1.y; acc[6] = b1.z; acc[7] = b1.w;
    } else if (q == 1) {
        float ds = g_dis[warp];
        float sw = ds * ds;
        uint4 u = *(const uint4*)(tmp + (size_t)warp * 64 + ql * 8);
        float f[8]; bf8_to_f32(u, f);
#pragma unroll
        for (int k = 0; k < 8; k++) acc[k] = sw * f[k];
    } else {
#pragma unroll
        for (int k = 0; k < 8; k++) acc[k] = 0.f;
    }

    for (int e = beg; e < end; e += 32) {
        unsigned long long cw = 0;
        if (e + lane < end) cw = __ldg(&g_ecw[e + lane]);
        int cnt = min(32, end - e);
#pragma unroll 2
        for (int j = 0; j < cnt; j += 4) {   // 4 edges per iteration
            unsigned long long s = __shfl_sync(0xffffffffu, cw, j + q);
            int   cj = (int)(unsigned)s;
            float wj = __uint_as_float((unsigned)(s >> 32));
            uint4 u = *(const uint4*)(tmp + (size_t)cj * 64 + ql * 8);
            float f[8]; bf8_to_f32(u, f);
#pragma unroll
            for (int k = 0; k < 8; k++) acc[k] = fmaf(wj, f[k], acc[k]);
        }
    }
#pragma unroll
    for (int k = 0; k < 8; k++) {
        acc[k] += __shfl_xor_sync(0xffffffffu, acc[k], 8);
        acc[k] += __shfl_xor_sync(0xffffffffu, acc[k], 16);
    }
    if (q < 2) {
        float4 v = make_float4(acc[q * 4 + 0], acc[q * 4 + 1], acc[q * 4 + 2], acc[q * 4 + 3]);
        *(float4*)(out + (size_t)warp * 64 + ql * 8 + q * 4) = v;
    }
}

// ---------------- launcher --------------------------------------------------
extern "C" void kernel_launch(void* const* d_in, const int* in_sizes, int n_in,
                              void* d_out, int out_size)
{
    const float* x  = (const float*)d_in[0];
    const int*   ei = (const int*)  d_in[1];
    const float* W0 = (const float*)d_in[2];
    const float* b0 = (const float*)d_in[3];
    const float* W1 = (const float*)d_in[4];
    const float* b1 = (const float*)d_in[5];
    const float* W2 = (const float*)d_in[6];
    const float* b2 = (const float*)d_in[7];
    float* out = (float*)d_out;

    const int N = in_sizes[0] / 128;
    const int E = in_sizes[1] / 2;
    const int* rows = ei;
    const int* cols = ei + E;

    __nv_bfloat16 *tmpb, *w0img, *w1img, *w2img;
    float* h;
    cudaGetSymbolAddress((void**)&tmpb,  g_tmpb);
    cudaGetSymbolAddress((void**)&h,     g_h);
    cudaGetSymbolAddress((void**)&w0img, g_w0img);
    cudaGetSymbolAddress((void**)&w1img, g_w1img);
    cudaGetSymbolAddress((void**)&w2img, g_w2img);
    __nv_bfloat16* w0_hi = w0img; __nv_bfloat16* w0_mi = w0img + 128 * PITCH;
    __nv_bfloat16* w1_hi = w1img; __nv_bfloat16* w1_mi = w1img + 128 * PITCH;
    __nv_bfloat16* w2_hi = w2img; __nv_bfloat16* w2_mi = w2img + 64 * PITCH;

    const int smem128 = (2 * 64 + 2 * 128) * PITCH * 2;   // 104448
    const int smem64  = (2 * 64 + 2 * 64)  * PITCH * 2;   // 69632
    static bool attr_done = false;
    if (!attr_done) {
        cudaFuncSetAttribute(k_gemm_mma<128, false>, cudaFuncAttributeMaxDynamicSharedMemorySize, smem128);
        cudaFuncSetAttribute(k_gemm_mma<128, true>,  cudaFuncAttributeMaxDynamicSharedMemorySize, smem128);
        cudaFuncSetAttribute(k_gemm_mma<64,  true>,  cudaFuncAttributeMaxDynamicSharedMemorySize, smem64);
        attr_done = true;
    }

    const int nb1024 = (N + 1023) / 1024;
    const int gemm_blocks = (N + 63) / 64;
    const int spmm_blocks = (N + 7) / 8;

    // 0-3: deg zero, split, count, GEMM0 (GEMM0 has no CSR dependency)
    k_deg_zero <<<(N + 255) / 256, 256>>>(N);
    k_split_all<<<(40960 + 255) / 256, 256>>>(W0, W1, W2);
    k_count    <<<(E + 255) / 256, 256>>>(rows, E);
    k_gemm_mma<128, false><<<gemm_blocks, 256, smem128>>>(x, w0_hi, w0_mi, tmpb, N);

    // 4-7: rest of CSR build
    k_disscan1<<<nb1024, 1024>>>(N);
    k_scan2   <<<1, 128>>>(nb1024);
    k_scan3   <<<nb1024, 1024>>>(N, E);
    k_fill    <<<(E + 255) / 256, 256>>>(rows, cols, E);

    // 8-12: SPMM0, then layers 1-2
    k_spmm128<<<spmm_blocks, 256>>>(tmpb, b0, h, N);
    k_gemm_mma<128, true><<<gemm_blocks, 256, smem128>>>(h, w1_hi, w1_mi, tmpb, N);
    k_spmm128<<<spmm_blocks, 256>>>(tmpb, b1, h, N);
    k_gemm_mma<64, true><<<gemm_blocks, 256, smem64>>>(h, w2_hi, w2_mi, tmpb, N);
    k_spmm64 <<<spmm_blocks, 256>>>(tmpb, b2, out, N);
}

// round 6
// speedup vs baseline: 1.0695x; 1.0695x over previous
#include <cuda_runtime.h>
#include <cuda_bf16.h>
#include <cstdint>
#include <math.h>

#define MAXN 100000
#define MAXE 1600000
#define PITCH 136   // bf16 elements per smem/W-image row (128 + 8 pad)

// ---------------- scratch (device globals; no allocation allowed) ----------
__device__ alignas(256) __nv_bfloat16 g_tmpb[(size_t)MAXN * 128];  // GEMM out (bf16)
__device__ alignas(256) float g_h[(size_t)MAXN * 128];             // hidden (fp32)
__device__ float g_dis[MAXN];
__device__ int   g_deg[MAXN];
__device__ int   g_rowptr[MAXN + 1];
__device__ int   g_cur[MAXN];
__device__ alignas(16) unsigned long long g_ecw[MAXE];  // packed {w_bits, col}
__device__ int   g_aux[1024];
__device__ alignas(16) __nv_bfloat16 g_w0img[2][128 * PITCH];
__device__ alignas(16) __nv_bfloat16 g_w1img[2][128 * PITCH];
__device__ alignas(16) __nv_bfloat16 g_w2img[2][64 * PITCH];

// ---------------- helpers ---------------------------------------------------
__device__ __forceinline__ uint32_t smem_u32(const void* p) {
    uint32_t a;
    asm("{ .reg .u64 t; cvta.to.shared.u64 t, %1; cvt.u32.u64 %0, t; }" : "=r"(a) : "l"(p));
    return a;
}
__device__ __forceinline__ void ldmx4(uint32_t& a0, uint32_t& a1, uint32_t& a2, uint32_t& a3,
                                      uint32_t addr) {
    asm volatile("ldmatrix.sync.aligned.m8n8.x4.shared.b16 {%0,%1,%2,%3}, [%4];"
                 : "=r"(a0), "=r"(a1), "=r"(a2), "=r"(a3) : "r"(addr));
}
__device__ __forceinline__ void ldmx2(uint32_t& b0, uint32_t& b1, uint32_t addr) {
    asm volatile("ldmatrix.sync.aligned.m8n8.x2.shared.b16 {%0,%1}, [%2];"
                 : "=r"(b0), "=r"(b1) : "r"(addr));
}
__device__ __forceinline__ void mma16816(float* c, uint32_t a0, uint32_t a1, uint32_t a2,
                                         uint32_t a3, uint32_t b0, uint32_t b1) {
    asm volatile("mma.sync.aligned.m16n8k16.row.col.f32.bf16.bf16.f32 "
                 "{%0,%1,%2,%3}, {%4,%5,%6,%7}, {%8,%9}, {%0,%1,%2,%3};"
                 : "+f"(c[0]), "+f"(c[1]), "+f"(c[2]), "+f"(c[3])
                 : "r"(a0), "r"(a1), "r"(a2), "r"(a3), "r"(b0), "r"(b1));
}

// ---------------- degree / normalization / CSR build -----------------------
__global__ void k_deg_zero(int n) {
    int i = blockIdx.x * blockDim.x + threadIdx.x;
    if (i < n) g_deg[i] = 0;
}
__global__ void k_count(const int* __restrict__ rows, int E) {
    int e = blockIdx.x * blockDim.x + threadIdx.x;
    if (e < E) atomicAdd(&g_deg[rows[e]], 1);
}
__global__ void k_disscan1(int n) {
    __shared__ int sh[1024];
    int tid = threadIdx.x;
    int i = blockIdx.x * 1024 + tid;
    int v = (i < n) ? g_deg[i] : 0;
    if (i < n) g_dis[i] = rsqrtf((float)(v + 1));
    sh[tid] = v;
    __syncthreads();
#pragma unroll
    for (int off = 1; off < 1024; off <<= 1) {
        int t = (tid >= off) ? sh[tid - off] : 0;
        __syncthreads();
        sh[tid] += t;
        __syncthreads();
    }
    if (i < n) g_rowptr[i] = sh[tid] - v;
    if (tid == 1023) g_aux[blockIdx.x] = sh[1023];
}
__global__ void k_scan2(int nb) {
    __shared__ int sh[128];
    int t = threadIdx.x;
    int v = (t < nb) ? g_aux[t] : 0;
    sh[t] = v;
    __syncthreads();
#pragma unroll
    for (int off = 1; off < 128; off <<= 1) {
        int x = (t >= off) ? sh[t - off] : 0;
        __syncthreads();
        sh[t] += x;
        __syncthreads();
    }
    if (t < nb) g_aux[t] = sh[t] - v;
}
__global__ void k_scan3(int n, int E) {
    int i = blockIdx.x * 1024 + threadIdx.x;
    if (i < n) {
        int v = g_rowptr[i] + g_aux[blockIdx.x];
        g_rowptr[i] = v;
        g_cur[i] = v;
    }
    if (blockIdx.x == 0 && threadIdx.x == 0) g_rowptr[n] = E;
}
__global__ void k_fill(const int* __restrict__ rows, const int* __restrict__ cols, int E) {
    int e = blockIdx.x * blockDim.x + threadIdx.x;
    if (e >= E) return;
    int r = rows[e], c = cols[e];
    int pos = atomicAdd(&g_cur[r], 1);
    float w = g_dis[r] * g_dis[c];
    g_ecw[pos] = ((unsigned long long)__float_as_uint(w) << 32) | (unsigned)c;
}

// ---------------- fused weight split ----------------------------------------
__global__ void k_split_all(const float* __restrict__ W0, const float* __restrict__ W1,
                            const float* __restrict__ W2)
{
    int idx = blockIdx.x * blockDim.x + threadIdx.x;
    const float* W;
    __nv_bfloat16 *hi, *mid;
    int BN, off;
    if (idx < 16384)        { W = W0; hi = g_w0img[0]; mid = g_w0img[1]; BN = 128; off = idx; }
    else if (idx < 32768)   { W = W1; hi = g_w1img[0]; mid = g_w1img[1]; BN = 128; off = idx - 16384; }
    else if (idx < 40960)   { W = W2; hi = g_w2img[0]; mid = g_w2img[1]; BN = 64;  off = idx - 32768; }
    else return;
    int k = off / BN, j = off % BN;
    float v = W[off];
    __nv_bfloat16 h = __float2bfloat16_rn(v);
    float r = v - __bfloat162float(h);
    hi [j * PITCH + k] = h;
    mid[j * PITCH + k] = __float2bfloat16_rn(r);
}

// ---------------- persistent GEMM via mma.sync bf16 split -------------------
// C[n,BN](bf16) = act(A[n,128]) @ W; CTA loops over 64-row tiles, W loaded once.
template <int BN, bool RELU>
__global__ __launch_bounds__(256, 2) void k_gemm_mma(
    const float* __restrict__ A,
    const __nv_bfloat16* __restrict__ WThi, const __nv_bfloat16* __restrict__ WTmid,
    __nv_bfloat16* __restrict__ C, int n, int ntiles)
{
    extern __shared__ __nv_bfloat16 sm[];
    __nv_bfloat16* Ahi = sm;                       // [64][PITCH]
    __nv_bfloat16* Ami = sm + 64 * PITCH;
    __nv_bfloat16* Whi = sm + 2 * 64 * PITCH;      // [BN][PITCH] x2 (hi, mid)

    const int tid = threadIdx.x;
    const int wid = tid >> 5;
    const int lane = tid & 31;
    constexpr int NT = BN / 32;
    constexpr uint32_t AOFF = 64 * PITCH * 2;
    constexpr uint32_t WOFF = BN * PITCH * 2;

    // W images once per CTA
    {
        const float4* s0 = (const float4*)WThi;
        const float4* s1 = (const float4*)WTmid;
        float4* d0 = (float4*)Whi;
        float4* d1 = (float4*)(Whi + BN * PITCH);
        constexpr int NV = BN * PITCH / 8;
#pragma unroll
        for (int i = tid; i < NV; i += 256) { d0[i] = s0[i]; d1[i] = s1[i]; }
    }

    const int warpM = wid & 1;
    const int warpN = wid >> 1;

    // invariant ldmatrix base addresses
    uint32_t a_addr[2], b_addr[NT];
#pragma unroll
    for (int mi = 0; mi < 2; mi++) {
        int r = warpM * 32 + mi * 16 + (lane & 15);
        int c = ((lane >> 4) << 3);
        a_addr[mi] = smem_u32(Ahi + r * PITCH + c);
    }
#pragma unroll
    for (int ni = 0; ni < NT; ni++) {
        int r = warpN * (BN / 4) + ni * 8 + (lane & 7);
        int c = ((lane >> 3) & 1) * 8;
        b_addr[ni] = smem_u32(Whi + r * PITCH + c);
    }

    const int cr = tid >> 2;       // conversion row (0..63)
    const int cq = tid & 3;        // conversion col quarter

    for (int tile = blockIdx.x; tile < ntiles; tile += gridDim.x) {
        const int row0 = tile * 64;

        // convert A tile: 64 x 128 fp32 -> hi/mid bf16 smem
        {
            const int gr = row0 + cr;
            const bool valid = gr < n;
            const float4* arow = (const float4*)(A + (size_t)(valid ? gr : 0) * 128);
#pragma unroll
            for (int i = 0; i < 8; i++) {
                int c = cq * 32 + i * 4;
                float4 v = valid ? arow[c >> 2] : make_float4(0.f, 0.f, 0.f, 0.f);
                if (RELU) {
                    v.x = fmaxf(v.x, 0.f); v.y = fmaxf(v.y, 0.f);
                    v.z = fmaxf(v.z, 0.f); v.w = fmaxf(v.w, 0.f);
                }
                __nv_bfloat162 h01 = __float22bfloat162_rn(make_float2(v.x, v.y));
                __nv_bfloat162 h23 = __float22bfloat162_rn(make_float2(v.z, v.w));
                float2 f01 = __bfloat1622float2(h01);
                float2 f23 = __bfloat1622float2(h23);
                __nv_bfloat162 m01 = __float22bfloat162_rn(make_float2(v.x - f01.x, v.y - f01.y));
                __nv_bfloat162 m23 = __float22bfloat162_rn(make_float2(v.z - f23.x, v.w - f23.y));
                *reinterpret_cast<uint2*>(Ahi + cr * PITCH + c) =
                    make_uint2(reinterpret_cast<uint32_t&>(h01), reinterpret_cast<uint32_t&>(h23));
                *reinterpret_cast<uint2*>(Ami + cr * PITCH + c) =
                    make_uint2(reinterpret_cast<uint32_t&>(m01), reinterpret_cast<uint32_t&>(m23));
            }
        }
        __syncthreads();

        float acc[2][NT][4];
#pragma unroll
        for (int mi = 0; mi < 2; mi++)
#pragma unroll
            for (int ni = 0; ni < NT; ni++)
#pragma unroll
                for (int j = 0; j < 4; j++) acc[mi][ni][j] = 0.f;

#pragma unroll
        for (int p = 0; p < 3; p++) {
            const uint32_t ao = (p == 2) ? AOFF : 0u;
            const uint32_t bo = (p == 1) ? WOFF : 0u;
#pragma unroll
            for (int kk = 0; kk < 8; kk++) {
                const uint32_t ko = kk * 32;
                uint32_t a[2][4];
#pragma unroll
                for (int mi = 0; mi < 2; mi++)
                    ldmx4(a[mi][0], a[mi][1], a[mi][2], a[mi][3], a_addr[mi] + ao + ko);
                uint32_t b[NT][2];
#pragma unroll
                for (int ni = 0; ni < NT; ni++)
                    ldmx2(b[ni][0], b[ni][1], b_addr[ni] + bo + ko);
#pragma unroll
                for (int mi = 0; mi < 2; mi++)
#pragma unroll
                    for (int ni = 0; ni < NT; ni++)
                        mma16816(acc[mi][ni], a[mi][0], a[mi][1], a[mi][2], a[mi][3],
                                 b[ni][0], b[ni][1]);
            }
        }

        // epilogue: bf16 stores
#pragma unroll
        for (int mi = 0; mi < 2; mi++) {
            int r = row0 + warpM * 32 + mi * 16 + (lane >> 2);
#pragma unroll
            for (int ni = 0; ni < NT; ni++) {
                int c = warpN * (BN / 4) + ni * 8 + (lane & 3) * 2;
                if (r < n) {
                    __nv_bfloat162 v = __float22bfloat162_rn(make_float2(acc[mi][ni][0], acc[mi][ni][1]));
                    *reinterpret_cast<__nv_bfloat162*>(C + (size_t)r * BN + c) = v;
                }
                if (r + 8 < n) {
                    __nv_bfloat162 v = __float22bfloat162_rn(make_float2(acc[mi][ni][2], acc[mi][ni][3]));
                    *reinterpret_cast<__nv_bfloat162*>(C + (size_t)(r + 8) * BN + c) = v;
                }
            }
        }
        __syncthreads();   // A smem reused next iteration
    }
}

// ---------------- SPMM (round-4 style: warp per row, broadcast per edge) ----
template <int D>
__global__ __launch_bounds__(256) void k_spmm(
    const __nv_bfloat16* __restrict__ tmp, const float* __restrict__ bias,
    float* __restrict__ out, int n)
{
    int warp = (blockIdx.x * 256 + threadIdx.x) >> 5;
    int lane = threadIdx.x & 31;
    if (warp >= n) return;
    int beg = __ldg(&g_rowptr[warp]);
    int end = __ldg(&g_rowptr[warp + 1]);
    float ds = g_dis[warp];
    float sw = ds * ds;

    if (D == 128) {
        float4 acc = *reinterpret_cast<const float4*>(bias + lane * 4);
        {
            uint2 u = *reinterpret_cast<const uint2*>(tmp + (size_t)warp * 128 + lane * 4);
            float2 p0 = __bfloat1622float2(reinterpret_cast<__nv_bfloat162&>(u.x));
            float2 p1 = __bfloat1622float2(reinterpret_cast<__nv_bfloat162&>(u.y));
            acc.x = fmaf(sw, p0.x, acc.x); acc.y = fmaf(sw, p0.y, acc.y);
            acc.z = fmaf(sw, p1.x, acc.z); acc.w = fmaf(sw, p1.y, acc.w);
        }
        for (int e = beg; e < end; e += 32) {
            unsigned long long cw = 0;
            if (e + lane < end) cw = __ldg(&g_ecw[e + lane]);
            int cnt = min(32, end - e);
#pragma unroll 4
            for (int j = 0; j < cnt; j++) {
                unsigned long long s = __shfl_sync(0xffffffffu, cw, j);
                int   cj = (int)(unsigned)s;
                float wj = __uint_as_float((unsigned)(s >> 32));
                uint2 u = *reinterpret_cast<const uint2*>(tmp + (size_t)cj * 128 + lane * 4);
                float2 p0 = __bfloat1622float2(reinterpret_cast<__nv_bfloat162&>(u.x));
                float2 p1 = __bfloat1622float2(reinterpret_cast<__nv_bfloat162&>(u.y));
                acc.x = fmaf(wj, p0.x, acc.x); acc.y = fmaf(wj, p0.y, acc.y);
                acc.z = fmaf(wj, p1.x, acc.z); acc.w = fmaf(wj, p1.y, acc.w);
            }
        }
        *reinterpret_cast<float4*>(out + (size_t)warp * 128 + lane * 4) = acc;
    } else {  // D == 64
        float2 acc = *reinterpret_cast<const float2*>(bias + lane * 2);
        {
            uint32_t u = *reinterpret_cast<const uint32_t*>(tmp + (size_t)warp * 64 + lane * 2);
            float2 p = __bfloat1622float2(reinterpret_cast<__nv_bfloat162&>(u));
            acc.x = fmaf(sw, p.x, acc.x); acc.y = fmaf(sw, p.y, acc.y);
        }
        for (int e = beg; e < end; e += 32) {
            unsigned long long cw = 0;
            if (e + lane < end) cw = __ldg(&g_ecw[e + lane]);
            int cnt = min(32, end - e);
#pragma unroll 4
            for (int j = 0; j < cnt; j++) {
                unsigned long long s = __shfl_sync(0xffffffffu, cw, j);
                int   cj = (int)(unsigned)s;
                float wj = __uint_as_float((unsigned)(s >> 32));
                uint32_t u = *reinterpret_cast<const uint32_t*>(tmp + (size_t)cj * 64 + lane * 2);
                float2 p = __bfloat1622float2(reinterpret_cast<__nv_bfloat162&>(u));
                acc.x = fmaf(wj, p.x, acc.x); acc.y = fmaf(wj, p.y, acc.y);
            }
        }
        *reinterpret_cast<float2*>(out + (size_t)warp * 64 + lane * 2) = acc;
    }
}

// ---------------- launcher --------------------------------------------------
extern "C" void kernel_launch(void* const* d_in, const int* in_sizes, int n_in,
                              void* d_out, int out_size)
{
    const float* x  = (const float*)d_in[0];
    const int*   ei = (const int*)  d_in[1];
    const float* W0 = (const float*)d_in[2];
    const float* b0 = (const float*)d_in[3];
    const float* W1 = (const float*)d_in[4];
    const float* b1 = (const float*)d_in[5];
    const float* W2 = (const float*)d_in[6];
    const float* b2 = (const float*)d_in[7];
    float* out = (float*)d_out;

    const int N = in_sizes[0] / 128;
    const int E = in_sizes[1] / 2;
    const int* rows = ei;
    const int* cols = ei + E;

    __nv_bfloat16 *tmpb, *w0img, *w1img, *w2img;
    float* h;
    cudaGetSymbolAddress((void**)&tmpb,  g_tmpb);
    cudaGetSymbolAddress((void**)&h,     g_h);
    cudaGetSymbolAddress((void**)&w0img, g_w0img);
    cudaGetSymbolAddress((void**)&w1img, g_w1img);
    cudaGetSymbolAddress((void**)&w2img, g_w2img);
    __nv_bfloat16* w0_hi = w0img; __nv_bfloat16* w0_mi = w0img + 128 * PITCH;
    __nv_bfloat16* w1_hi = w1img; __nv_bfloat16* w1_mi = w1img + 128 * PITCH;
    __nv_bfloat16* w2_hi = w2img; __nv_bfloat16* w2_mi = w2img + 64 * PITCH;

    const int smem128 = (2 * 64 + 2 * 128) * PITCH * 2;   // 104448
    const int smem64  = (2 * 64 + 2 * 64)  * PITCH * 2;   // 69632
    static bool attr_done = false;
    if (!attr_done) {
        cudaFuncSetAttribute(k_gemm_mma<128, false>, cudaFuncAttributeMaxDynamicSharedMemorySize, smem128);
        cudaFuncSetAttribute(k_gemm_mma<128, true>,  cudaFuncAttributeMaxDynamicSharedMemorySize, smem128);
        cudaFuncSetAttribute(k_gemm_mma<64,  true>,  cudaFuncAttributeMaxDynamicSharedMemorySize, smem64);
        attr_done = true;
    }

    const int nb1024 = (N + 1023) / 1024;
    const int gtiles = (N + 63) / 64;
    const int gemm_grid = gtiles < 296 ? gtiles : 296;   // 2 CTAs/SM x 148 SMs
    const int spmm_blocks = (N + 7) / 8;

    // 0-3: deg zero, split, count, GEMM0 (no CSR dependency)
    k_deg_zero <<<(N + 255) / 256, 256>>>(N);
    k_split_all<<<(40960 + 255) / 256, 256>>>(W0, W1, W2);
    k_count    <<<(E + 255) / 256, 256>>>(rows, E);
    k_gemm_mma<128, false><<<gemm_grid, 256, smem128>>>(x, w0_hi, w0_mi, tmpb, N, gtiles);

    // 4-7: rest of CSR build
    k_disscan1<<<nb1024, 1024>>>(N);
    k_scan2   <<<1, 128>>>(nb1024);
    k_scan3   <<<nb1024, 1024>>>(N, E);
    k_fill    <<<(E + 255) / 256, 256>>>(rows, cols, E);

    // 8-12: layers
    k_spmm<128><<<spmm_blocks, 256>>>(tmpb, b0, h, N);
    k_gemm_mma<128, true><<<gemm_grid, 256, smem128>>>(h, w1_hi, w1_mi, tmpb, N, gtiles);
    k_spmm<128><<<spmm_blocks, 256>>>(tmpb, b1, h, N);
    k_gemm_mma<64, true><<<gemm_grid, 256, smem64>>>(h, w2_hi, w2_mi, tmpb, N, gtiles);
    k_spmm<64> <<<spmm_blocks, 256>>>(tmpb, b2, out, N);
}

// round 7
// speedup vs baseline: 1.1654x; 1.0897x over previous
#include <cuda_runtime.h>
#include <cuda_bf16.h>
#include <cstdint>
#include <math.h>

#define MAXN 100000
#define MAXE 1600000
#define PITCH 136   // bf16 elements per smem row (128 + 8 pad); 272 bytes

// ---------------- scratch (device globals; no allocation allowed) ----------
__device__ alignas(256) __nv_bfloat16 g_tmpb[(size_t)MAXN * 128];  // GEMM out
__device__ alignas(256) __nv_bfloat16 g_hhi[(size_t)MAXN * 128];   // hidden hi
__device__ alignas(256) __nv_bfloat16 g_hmi[(size_t)MAXN * 128];   // hidden mid
__device__ alignas(256) __nv_bfloat16 g_xhi[(size_t)MAXN * 128];   // x hi
__device__ alignas(256) __nv_bfloat16 g_xmi[(size_t)MAXN * 128];   // x mid
__device__ float g_dis[MAXN];
__device__ int   g_deg[MAXN];
__device__ int   g_rowptr[MAXN + 1];
__device__ int   g_cur[MAXN];
__device__ alignas(16) unsigned long long g_ecw[MAXE];  // packed {w_bits, col}
__device__ int   g_aux[1024];
__device__ alignas(16) __nv_bfloat16 g_w0img[2][128 * PITCH];
__device__ alignas(16) __nv_bfloat16 g_w1img[2][128 * PITCH];
__device__ alignas(16) __nv_bfloat16 g_w2img[2][64 * PITCH];

// ---------------- helpers ---------------------------------------------------
__device__ __forceinline__ uint32_t smem_u32(const void* p) {
    uint32_t a;
    asm("{ .reg .u64 t; cvta.to.shared.u64 t, %1; cvt.u32.u64 %0, t; }" : "=r"(a) : "l"(p));
    return a;
}
__device__ __forceinline__ void ldmx4(uint32_t* r, uint32_t addr) {
    asm volatile("ldmatrix.sync.aligned.m8n8.x4.shared.b16 {%0,%1,%2,%3}, [%4];"
                 : "=r"(r[0]), "=r"(r[1]), "=r"(r[2]), "=r"(r[3]) : "r"(addr));
}
__device__ __forceinline__ void mma16816(float* c, const uint32_t* a, uint32_t b0, uint32_t b1) {
    asm volatile("mma.sync.aligned.m16n8k16.row.col.f32.bf16.bf16.f32 "
                 "{%0,%1,%2,%3}, {%4,%5,%6,%7}, {%8,%9}, {%0,%1,%2,%3};"
                 : "+f"(c[0]), "+f"(c[1]), "+f"(c[2]), "+f"(c[3])
                 : "r"(a[0]), "r"(a[1]), "r"(a[2]), "r"(a[3]), "r"(b0), "r"(b1));
}
#define CP_ASYNC16(dst, src) \
    asm volatile("cp.async.cg.shared.global [%0], [%1], 16;" :: "r"(dst), "l"(src))
#define CP_COMMIT() asm volatile("cp.async.commit_group;")

// split one float -> (hi, mid) bf16
__device__ __forceinline__ void split1(float v, __nv_bfloat16& h, __nv_bfloat16& m) {
    h = __float2bfloat16_rn(v);
    m = __float2bfloat16_rn(v - __bfloat162float(h));
}

// ---------------- degree / normalization / CSR build -----------------------
__global__ void k_deg_zero(int n) {
    int i = blockIdx.x * blockDim.x + threadIdx.x;
    if (i < n) g_deg[i] = 0;
}
__global__ void k_count(const int* __restrict__ rows, int E) {
    int e = blockIdx.x * blockDim.x + threadIdx.x;
    if (e < E) atomicAdd(&g_deg[rows[e]], 1);
}
__global__ void k_disscan1(int n) {
    __shared__ int sh[1024];
    int tid = threadIdx.x;
    int i = blockIdx.x * 1024 + tid;
    int v = (i < n) ? g_deg[i] : 0;
    if (i < n) g_dis[i] = rsqrtf((float)(v + 1));
    sh[tid] = v;
    __syncthreads();
#pragma unroll
    for (int off = 1; off < 1024; off <<= 1) {
        int t = (tid >= off) ? sh[tid - off] : 0;
        __syncthreads();
        sh[tid] += t;
        __syncthreads();
    }
    if (i < n) g_rowptr[i] = sh[tid] - v;
    if (tid == 1023) g_aux[blockIdx.x] = sh[1023];
}
__global__ void k_scan2(int nb) {
    __shared__ int sh[128];
    int t = threadIdx.x;
    int v = (t < nb) ? g_aux[t] : 0;
    sh[t] = v;
    __syncthreads();
#pragma unroll
    for (int off = 1; off < 128; off <<= 1) {
        int x = (t >= off) ? sh[t - off] : 0;
        __syncthreads();
        sh[t] += x;
        __syncthreads();
    }
    if (t < nb) g_aux[t] = sh[t] - v;
}
__global__ void k_scan3(int n, int E) {
    int i = blockIdx.x * 1024 + threadIdx.x;
    if (i < n) {
        int v = g_rowptr[i] + g_aux[blockIdx.x];
        g_rowptr[i] = v;
        g_cur[i] = v;
    }
    if (blockIdx.x == 0 && threadIdx.x == 0) g_rowptr[n] = E;
}
__global__ void k_fill(const int* __restrict__ rows, const int* __restrict__ cols, int E) {
    int e = blockIdx.x * blockDim.x + threadIdx.x;
    if (e >= E) return;
    int r = rows[e], c = cols[e];
    int pos = atomicAdd(&g_cur[r], 1);
    float w = g_dis[r] * g_dis[c];
    g_ecw[pos] = ((unsigned long long)__float_as_uint(w) << 32) | (unsigned)c;
}

// ---------------- fused weight split ----------------------------------------
__global__ void k_split_all(const float* __restrict__ W0, const float* __restrict__ W1,
                            const float* __restrict__ W2)
{
    int idx = blockIdx.x * blockDim.x + threadIdx.x;
    const float* W;
    __nv_bfloat16 *hi, *mid;
    int BN, off;
    if (idx < 16384)        { W = W0; hi = g_w0img[0]; mid = g_w0img[1]; BN = 128; off = idx; }
    else if (idx < 32768)   { W = W1; hi = g_w1img[0]; mid = g_w1img[1]; BN = 128; off = idx - 16384; }
    else if (idx < 40960)   { W = W2; hi = g_w2img[0]; mid = g_w2img[1]; BN = 64;  off = idx - 32768; }
    else return;
    int k = off / BN, j = off % BN;
    __nv_bfloat16 h, m;
    split1(W[off], h, m);
    hi [j * PITCH + k] = h;
    mid[j * PITCH + k] = m;
}

// ---------------- x split: fp32 -> hi/mid bf16 ------------------------------
__global__ void k_convx(const float* __restrict__ x, __nv_bfloat16* __restrict__ hi,
                        __nv_bfloat16* __restrict__ mid, int total4)
{
    int idx = blockIdx.x * blockDim.x + threadIdx.x;   // one float4
    if (idx >= total4) return;
    float4 v = reinterpret_cast<const float4*>(x)[idx];
    __nv_bfloat16 h[4], m[4];
    split1(v.x, h[0], m[0]); split1(v.y, h[1], m[1]);
    split1(v.z, h[2], m[2]); split1(v.w, h[3], m[3]);
    *reinterpret_cast<uint2*>(hi + (size_t)idx * 4) = *reinterpret_cast<uint2*>(h);
    *reinterpret_cast<uint2*>(mid + (size_t)idx * 4) = *reinterpret_cast<uint2*>(m);
}

// ---------------- persistent GEMM: pre-split bf16 A, cp.async 2-stage -------
// C[n,BN](bf16) = A @ W with A = Ahi+Ami, W = Whi+Wmi; 3 products.
// 128-row tiles, 512 threads (16 warps: warpM=wid&3, warpN=wid>>2).
template <int BN>
__global__ __launch_bounds__(512, 1) void k_gemm_mma(
    const __nv_bfloat16* __restrict__ Ahi_g, const __nv_bfloat16* __restrict__ Ami_g,
    const __nv_bfloat16* __restrict__ WThi, const __nv_bfloat16* __restrict__ WTmid,
    __nv_bfloat16* __restrict__ C, int n, int ntiles)
{
    extern __shared__ __nv_bfloat16 sm[];
    constexpr int WIMG = BN * PITCH;       // elements per W image
    constexpr int AIMG = 128 * PITCH;      // elements per A image
    __nv_bfloat16* Wsm = sm;               // [hi | mid]
    __nv_bfloat16* Asm = sm + 2 * WIMG;    // [stage][hi | mid]

    const int tid = threadIdx.x;
    const int wid = tid >> 5;
    const int lane = tid & 31;
    constexpr int NI = BN / 32;            // n8 tiles per warp (4 or 2)
    constexpr int NB4 = NI / 2;            // ldmx4 B loads per type (2 or 1)

    // W images -> smem once
    {
        const float4* s0 = (const float4*)WThi;
        const float4* s1 = (const float4*)WTmid;
        float4* d0 = (float4*)Wsm;
        float4* d1 = (float4*)(Wsm + WIMG);
        constexpr int NV = WIMG / 8;
#pragma unroll
        for (int i = tid; i < NV; i += 512) { d0[i] = s0[i]; d1[i] = s1[i]; }
    }

    const int warpM = wid & 3;
    const int warpN = wid >> 2;

    // invariant ldmatrix addresses (bytes)
    uint32_t a_addr[2], b_addr[NB4];
    {
        uint32_t abase = smem_u32(Asm);
#pragma unroll
        for (int mi = 0; mi < 2; mi++) {
            int r = warpM * 32 + mi * 16 + (lane & 15);
            int c = (lane >> 4) << 3;
            a_addr[mi] = abase + r * (PITCH * 2) + c * 2;
        }
        uint32_t bbase = smem_u32(Wsm);
#pragma unroll
        for (int ni2 = 0; ni2 < NB4; ni2++) {
            int r = warpN * (BN / 4) + ni2 * 16 + ((lane >> 4) & 1) * 8 + (lane & 7);
            int c = ((lane >> 3) & 1) * 8;
            b_addr[ni2] = bbase + r * (PITCH * 2) + c * 2;
        }
    }

    auto issue_copy = [&](int tile, int s) {
        const int row0 = tile * 128;
        const uint32_t dst_base = smem_u32(Asm) + (uint32_t)s * (2 * AIMG * 2);
#pragma unroll
        for (int i = 0; i < 8; i++) {
            int idx = tid + i * 512;
            int arr = idx >> 11;            // 0: hi, 1: mid
            int row = (idx >> 4) & 127;
            int ch  = idx & 15;
            int gr = row0 + row;
            if (gr >= n) gr = n - 1;        // clamp (result unused)
            const __nv_bfloat16* src = (arr ? Ami_g : Ahi_g) + (size_t)gr * 128 + ch * 8;
            uint32_t dst = dst_base + (uint32_t)arr * (AIMG * 2) + row * (PITCH * 2) + ch * 16;
            CP_ASYNC16(dst, src);
        }
    };

    int tile = blockIdx.x;
    int s = 0;
    if (tile < ntiles) issue_copy(tile, 0);
    CP_COMMIT();

    for (; tile < ntiles; tile += gridDim.x) {
        const int next = tile + gridDim.x;
        if (next < ntiles) {
            issue_copy(next, s ^ 1);
            CP_COMMIT();
            asm volatile("cp.async.wait_group 1;");
        } else {
            asm volatile("cp.async.wait_group 0;");
        }
        __syncthreads();

        const uint32_t ab = (uint32_t)s * (2 * AIMG * 2);

        float acc[2][NI][4];
#pragma unroll
        for (int mi = 0; mi < 2; mi++)
#pragma unroll
            for (int ni = 0; ni < NI; ni++)
#pragma unroll
                for (int j = 0; j < 4; j++) acc[mi][ni][j] = 0.f;

#pragma unroll
        for (int kk = 0; kk < 8; kk++) {
            const uint32_t ko = kk * 32;
            uint32_t ah[2][4], am[2][4];
#pragma unroll
            for (int mi = 0; mi < 2; mi++) {
                ldmx4(ah[mi], a_addr[mi] + ab + ko);
                ldmx4(am[mi], a_addr[mi] + ab + (AIMG * 2) + ko);
            }
            uint32_t bh[NB4][4], bm[NB4][4];
#pragma unroll
            for (int ni2 = 0; ni2 < NB4; ni2++) {
                ldmx4(bh[ni2], b_addr[ni2] + ko);
                ldmx4(bm[ni2], b_addr[ni2] + (WIMG * 2) + ko);
            }
#pragma unroll
            for (int mi = 0; mi < 2; mi++)
#pragma unroll
                for (int ni = 0; ni < NI; ni++) {
                    const uint32_t* bhp = &bh[ni >> 1][(ni & 1) * 2];
                    const uint32_t* bmp = &bm[ni >> 1][(ni & 1) * 2];
                    mma16816(acc[mi][ni], ah[mi], bhp[0], bhp[1]);   // hi*hi
                    mma16816(acc[mi][ni], ah[mi], bmp[0], bmp[1]);   // hi*mid
                    mma16816(acc[mi][ni], am[mi], bhp[0], bhp[1]);   // mid*hi
                }
        }

        // epilogue: bf16 stores
        const int row0 = tile * 128;
#pragma unroll
        for (int mi = 0; mi < 2; mi++) {
            int r = row0 + warpM * 32 + mi * 16 + (lane >> 2);
#pragma unroll
            for (int ni = 0; ni < NI; ni++) {
                int c = warpN * (BN / 4) + ni * 8 + (lane & 3) * 2;
                if (r < n) {
                    __nv_bfloat162 v = __float22bfloat162_rn(make_float2(acc[mi][ni][0], acc[mi][ni][1]));
                    *reinterpret_cast<__nv_bfloat162*>(C + (size_t)r * BN + c) = v;
                }
                if (r + 8 < n) {
                    __nv_bfloat162 v = __float22bfloat162_rn(make_float2(acc[mi][ni][2], acc[mi][ni][3]));
                    *reinterpret_cast<__nv_bfloat162*>(C + (size_t)(r + 8) * BN + c) = v;
                }
            }
        }
        s ^= 1;
        __syncthreads();   // protect stage being read before next overwrite
    }
}

// ---------------- SPMM (warp/row): optionally split-writes hi/mid bf16 ------
// out[r] = relu?(bias + dis^2*tmp[r] + sum w*tmp[c])
template <int D, bool RELU, bool SPLIT>
__global__ __launch_bounds__(256) void k_spmm(
    const __nv_bfloat16* __restrict__ tmp, const float* __restrict__ bias,
    float* __restrict__ outf, __nv_bfloat16* __restrict__ ohi,
    __nv_bfloat16* __restrict__ omi, int n)
{
    int warp = (blockIdx.x * 256 + threadIdx.x) >> 5;
    int lane = threadIdx.x & 31;
    if (warp >= n) return;
    int beg = __ldg(&g_rowptr[warp]);
    int end = __ldg(&g_rowptr[warp + 1]);
    float ds = g_dis[warp];
    float sw = ds * ds;

    if (D == 128) {
        float4 acc = *reinterpret_cast<const float4*>(bias + lane * 4);
        {
            uint2 u = *reinterpret_cast<const uint2*>(tmp + (size_t)warp * 128 + lane * 4);
            float2 p0 = __bfloat1622float2(reinterpret_cast<__nv_bfloat162&>(u.x));
            float2 p1 = __bfloat1622float2(reinterpret_cast<__nv_bfloat162&>(u.y));
            acc.x = fmaf(sw, p0.x, acc.x); acc.y = fmaf(sw, p0.y, acc.y);
            acc.z = fmaf(sw, p1.x, acc.z); acc.w = fmaf(sw, p1.y, acc.w);
        }
        for (int e = beg; e < end; e += 32) {
            unsigned long long cw = 0;
            if (e + lane < end) cw = __ldg(&g_ecw[e + lane]);
            int cnt = min(32, end - e);
#pragma unroll 4
            for (int j = 0; j < cnt; j++) {
                unsigned long long sv = __shfl_sync(0xffffffffu, cw, j);
                int   cj = (int)(unsigned)sv;
                float wj = __uint_as_float((unsigned)(sv >> 32));
                uint2 u = *reinterpret_cast<const uint2*>(tmp + (size_t)cj * 128 + lane * 4);
                float2 p0 = __bfloat1622float2(reinterpret_cast<__nv_bfloat162&>(u.x));
                float2 p1 = __bfloat1622float2(reinterpret_cast<__nv_bfloat162&>(u.y));
                acc.x = fmaf(wj, p0.x, acc.x); acc.y = fmaf(wj, p0.y, acc.y);
                acc.z = fmaf(wj, p1.x, acc.z); acc.w = fmaf(wj, p1.y, acc.w);
            }
        }
        if (RELU) {
            acc.x = fmaxf(acc.x, 0.f); acc.y = fmaxf(acc.y, 0.f);
            acc.z = fmaxf(acc.z, 0.f); acc.w = fmaxf(acc.w, 0.f);
        }
        if (SPLIT) {
            __nv_bfloat16 h[4], m[4];
            split1(acc.x, h[0], m[0]); split1(acc.y, h[1], m[1]);
            split1(acc.z, h[2], m[2]); split1(acc.w, h[3], m[3]);
            *reinterpret_cast<uint2*>(ohi + (size_t)warp * 128 + lane * 4) = *reinterpret_cast<uint2*>(h);
            *reinterpret_cast<uint2*>(omi + (size_t)warp * 128 + lane * 4) = *reinterpret_cast<uint2*>(m);
        } else {
            *reinterpret_cast<float4*>(outf + (size_t)warp * 128 + lane * 4) = acc;
        }
    } else {  // D == 64, fp32 out
        float2 acc = *reinterpret_cast<const float2*>(bias + lane * 2);
        {
            uint32_t u = *reinterpret_cast<const uint32_t*>(tmp + (size_t)warp * 64 + lane * 2);
            float2 p = __bfloat1622float2(reinterpret_cast<__nv_bfloat162&>(u));
            acc.x = fmaf(sw, p.x, acc.x); acc.y = fmaf(sw, p.y, acc.y);
        }
        for (int e = beg; e < end; e += 32) {
            unsigned long long cw = 0;
            if (e + lane < end) cw = __ldg(&g_ecw[e + lane]);
            int cnt = min(32, end - e);
#pragma unroll 4
            for (int j = 0; j < cnt; j++) {
                unsigned long long sv = __shfl_sync(0xffffffffu, cw, j);
                int   cj = (int)(unsigned)sv;
                float wj = __uint_as_float((unsigned)(sv >> 32));
                uint32_t u = *reinterpret_cast<const uint32_t*>(tmp + (size_t)cj * 64 + lane * 2);
                float2 p = __bfloat1622float2(reinterpret_cast<__nv_bfloat162&>(u));
                acc.x = fmaf(wj, p.x, acc.x); acc.y = fmaf(wj, p.y, acc.y);
            }
        }
        *reinterpret_cast<float2*>(outf + (size_t)warp * 64 + lane * 2) = acc;
    }
}

// ---------------- launcher --------------------------------------------------
extern "C" void kernel_launch(void* const* d_in, const int* in_sizes, int n_in,
                              void* d_out, int out_size)
{
    const float* x  = (const float*)d_in[0];
    const int*   ei = (const int*)  d_in[1];
    const float* W0 = (const float*)d_in[2];
    const float* b0 = (const float*)d_in[3];
    const float* W1 = (const float*)d_in[4];
    const float* b1 = (const float*)d_in[5];
    const float* W2 = (const float*)d_in[6];
    const float* b2 = (const float*)d_in[7];
    float* out = (float*)d_out;

    const int N = in_sizes[0] / 128;
    const int E = in_sizes[1] / 2;
    const int* rows = ei;
    const int* cols = ei + E;

    __nv_bfloat16 *tmpb, *hhi, *hmi, *xhi, *xmi, *w0img, *w1img, *w2img;
    cudaGetSymbolAddress((void**)&tmpb,  g_tmpb);
    cudaGetSymbolAddress((void**)&hhi,   g_hhi);
    cudaGetSymbolAddress((void**)&hmi,   g_hmi);
    cudaGetSymbolAddress((void**)&xhi,   g_xhi);
    cudaGetSymbolAddress((void**)&xmi,   g_xmi);
    cudaGetSymbolAddress((void**)&w0img, g_w0img);
    cudaGetSymbolAddress((void**)&w1img, g_w1img);
    cudaGetSymbolAddress((void**)&w2img, g_w2img);
    __nv_bfloat16* w0_hi = w0img; __nv_bfloat16* w0_mi = w0img + 128 * PITCH;
    __nv_bfloat16* w1_hi = w1img; __nv_bfloat16* w1_mi = w1img + 128 * PITCH;
    __nv_bfloat16* w2_hi = w2img; __nv_bfloat16* w2_mi = w2img + 64 * PITCH;

    // smem: W(2 images) + A(2 stages x 2 images of 128 rows)
    const int smem128 = (2 * 128 + 4 * 128) * PITCH * 2;   // 208896
    const int smem64  = (2 * 64  + 4 * 128) * PITCH * 2;   // 174080
    static bool attr_done = false;
    if (!attr_done) {
        cudaFuncSetAttribute(k_gemm_mma<128>, cudaFuncAttributeMaxDynamicSharedMemorySize, smem128);
        cudaFuncSetAttribute(k_gemm_mma<64>,  cudaFuncAttributeMaxDynamicSharedMemorySize, smem64);
        attr_done = true;
    }

    const int nb1024 = (N + 1023) / 1024;
    const int gtiles = (N + 127) / 128;
    const int gemm_grid = gtiles < 148 ? gtiles : 148;
    const int spmm_blocks = (N + 7) / 8;

    // prep (no CSR dependency for GEMM0)
    k_deg_zero <<<(N + 255) / 256, 256>>>(N);
    k_split_all<<<(40960 + 255) / 256, 256>>>(W0, W1, W2);
    k_convx    <<<(N * 32 + 255) / 256, 256>>>(x, xhi, xmi, N * 32);
    k_count    <<<(E + 255) / 256, 256>>>(rows, E);
    k_gemm_mma<128><<<gemm_grid, 512, smem128>>>(xhi, xmi, w0_hi, w0_mi, tmpb, N, gtiles);

    // rest of CSR build
    k_disscan1<<<nb1024, 1024>>>(N);
    k_scan2   <<<1, 128>>>(nb1024);
    k_scan3   <<<nb1024, 1024>>>(N, E);
    k_fill    <<<(E + 255) / 256, 256>>>(rows, cols, E);

    // layers
    k_spmm<128, true, true><<<spmm_blocks, 256>>>(tmpb, b0, nullptr, hhi, hmi, N);
    k_gemm_mma<128><<<gemm_grid, 512, smem128>>>(hhi, hmi, w1_hi, w1_mi, tmpb, N, gtiles);
    k_spmm<128, true, true><<<spmm_blocks, 256>>>(tmpb, b1, nullptr, hhi, hmi, N);
    k_gemm_mma<64><<<gemm_grid, 512, smem64>>>(hhi, hmi, w2_hi, w2_mi, tmpb, N, gtiles);
    k_spmm<64, false, false><<<spmm_blocks, 256>>>(tmpb, b2, out, nullptr, nullptr, N);
}